// round 15
// baseline (speedup 1.0000x reference)
#include <cuda_runtime.h>
#include <cuda_bf16.h>
#include <cuda_fp16.h>
#include <cstdint>

#define Bn 8
#define Cn 256
#define Ln 2048
#define Dn 32

__device__ __nv_bfloat16 g_Qb[Bn * Ln * Dn];
__device__ __nv_bfloat16 g_Kb[Bn * Ln * Dn];
__device__ __nv_bfloat16 g_Vb[Bn * Cn * Ln];

__device__ __forceinline__ uint32_t smem_to_u32(const void* p) {
    uint32_t a;
    asm("{ .reg .u64 t; cvta.to.shared.u64 t, %1; cvt.u32.u64 %0, t; }" : "=r"(a) : "l"(p));
    return a;
}
__device__ __forceinline__ float ex2f(float x) {
    float r; asm("ex2.approx.ftz.f32 %0, %1;" : "=f"(r) : "f"(x)); return r;
}
#define CVT_BF16X2(res, a, b) \
    asm("cvt.rn.bf16x2.f32 %0, %1, %2;" : "=r"(res) : "f"(b), "f"(a))
#define CVT_F16X2(res, a, b) \
    asm("cvt.rn.f16x2.f32 %0, %1, %2;" : "=r"(res) : "f"(b), "f"(a))

__device__ __forceinline__ void ldmatrix_x4(uint32_t& r0, uint32_t& r1, uint32_t& r2, uint32_t& r3, uint32_t addr) {
    asm volatile("ldmatrix.sync.aligned.m8n8.x4.shared.b16 {%0,%1,%2,%3}, [%4];"
                 : "=r"(r0), "=r"(r1), "=r"(r2), "=r"(r3) : "r"(addr));
}
__device__ __forceinline__ void ldmatrix_x2(uint32_t& r0, uint32_t& r1, uint32_t addr) {
    asm volatile("ldmatrix.sync.aligned.m8n8.x2.shared.b16 {%0,%1}, [%2];"
                 : "=r"(r0), "=r"(r1) : "r"(addr));
}
__device__ __forceinline__ void mma_bf16(float& c0, float& c1, float& c2, float& c3,
                                         uint32_t a0, uint32_t a1, uint32_t a2, uint32_t a3,
                                         uint32_t b0, uint32_t b1) {
    asm volatile("mma.sync.aligned.m16n8k16.row.col.f32.bf16.bf16.f32 "
                 "{%0,%1,%2,%3}, {%4,%5,%6,%7}, {%8,%9}, {%0,%1,%2,%3};"
                 : "+f"(c0), "+f"(c1), "+f"(c2), "+f"(c3)
                 : "r"(a0), "r"(a1), "r"(a2), "r"(a3), "r"(b0), "r"(b1));
}
__device__ __forceinline__ void mma_fp16(float& c0, float& c1, float& c2, float& c3,
                                         uint32_t a0, uint32_t a1, uint32_t a2, uint32_t a3,
                                         uint32_t b0, uint32_t b1) {
    asm volatile("mma.sync.aligned.m16n8k16.row.col.f32.f16.f16.f32 "
                 "{%0,%1,%2,%3}, {%4,%5,%6,%7}, {%8,%9}, {%0,%1,%2,%3};"
                 : "+f"(c0), "+f"(c1), "+f"(c2), "+f"(c3)
                 : "r"(a0), "r"(a1), "r"(a2), "r"(a3), "r"(b0), "r"(b1));
}
__device__ __forceinline__ void cp_async16(uint32_t saddr, const void* gptr) {
    asm volatile("cp.async.cg.shared.global [%0], [%1], 16;" :: "r"(saddr), "l"(gptr));
}
#define CP_COMMIT() asm volatile("cp.async.commit_group;" ::: "memory")
#define CP_WAIT0()  asm volatile("cp.async.wait_group 0;" ::: "memory")

// ===========================================================================
// Kernel 1: QKV projection as HMMA GEMM (unchanged).
// ===========================================================================
#define QKV_SMEM 69632

__global__ __launch_bounds__(512) void qkv_gemm(
    const float* __restrict__ x,
    const float* __restrict__ Wq, const float* __restrict__ bq,
    const float* __restrict__ Wk, const float* __restrict__ bk,
    const float* __restrict__ Wv, const float* __restrict__ bv)
{
    extern __shared__ __align__(16) char qsmraw[];
    uint32_t* xs = reinterpret_cast<uint32_t*>(qsmraw);

    const int b = blockIdx.y, l0 = blockIdx.x * 128, t = threadIdx.x;
    const float* xb = x + (size_t)b * Cn * Ln;

    for (int idx = t; idx < 128 * 128; idx += 512) {
        int cp = idx >> 7, l = idx & 127;
        float f0 = xb[(size_t)(2 * cp) * Ln + l0 + l];
        float f1 = xb[(size_t)(2 * cp + 1) * Ln + l0 + l];
        uint32_t p; CVT_F16X2(p, f0, f1);
        xs[l * 132 + cp] = p;
    }
    __syncthreads();

    const int w = t >> 5, lane = t & 31;
    const int mg = w & 1, nh = w >> 1;
    const int nbase = nh * 40;

    const float* wp[5];
    #pragma unroll
    for (int nt = 0; nt < 5; ++nt) {
        int n0 = nbase + nt * 8;
        const float* src;
        if (n0 < 32)      src = Wq + n0 * Cn;
        else if (n0 < 64) src = Wk + (n0 - 32) * Cn;
        else              src = Wv + (n0 - 64) * Cn;
        wp[nt] = src + (lane >> 2) * Cn + (lane & 3) * 2;
    }

    float of[4][5][4];
    #pragma unroll
    for (int m = 0; m < 4; ++m)
        #pragma unroll
        for (int n = 0; n < 5; ++n)
            #pragma unroll
            for (int k = 0; k < 4; ++k) of[m][n][k] = 0.f;

    const uint32_t abase = smem_to_u32(xs)
        + (uint32_t)((mg * 64 + (lane & 15)) * 132) * 4 + ((lane >> 4) & 1) * 16;

    for (int ks = 0; ks < 16; ++ks) {
        uint32_t aq[4][4];
        #pragma unroll
        for (int mt = 0; mt < 4; ++mt)
            ldmatrix_x4(aq[mt][0], aq[mt][1], aq[mt][2], aq[mt][3],
                        abase + (uint32_t)(mt * 16 * 132) * 4 + ks * 32);
        #pragma unroll
        for (int nt = 0; nt < 5; ++nt) {
            float2 wa = __ldg(reinterpret_cast<const float2*>(wp[nt] + ks * 16));
            float2 wb = __ldg(reinterpret_cast<const float2*>(wp[nt] + ks * 16 + 8));
            uint32_t b0, b1;
            CVT_F16X2(b0, wa.x, wa.y);
            CVT_F16X2(b1, wb.x, wb.y);
            #pragma unroll
            for (int mt = 0; mt < 4; ++mt)
                mma_fp16(of[mt][nt][0], of[mt][nt][1], of[mt][nt][2], of[mt][nt][3],
                         aq[mt][0], aq[mt][1], aq[mt][2], aq[mt][3], b0, b1);
        }
    }
    __syncthreads();

    __nv_bfloat16* vt = reinterpret_cast<__nv_bfloat16*>(qsmraw);
    const float qs = 1.4426950408889634f * 0.17677669529663687f;

    #pragma unroll
    for (int nt = 0; nt < 5; ++nt) {
        int n0 = nbase + nt * 8;
        int d = n0 + (lane & 3) * 2;
        float2 bs;
        if (n0 < 32)      bs = __ldg(reinterpret_cast<const float2*>(bq + d));
        else if (n0 < 64) bs = __ldg(reinterpret_cast<const float2*>(bk + d - 32));
        else              bs = __ldg(reinterpret_cast<const float2*>(bv + d - 64));
        #pragma unroll
        for (int mt = 0; mt < 4; ++mt) {
            const int ll = mg * 64 + mt * 16 + (lane >> 2);
            const int lq = l0 + ll;
            float v0 = of[mt][nt][0] + bs.x, v1 = of[mt][nt][1] + bs.y;
            float v2 = of[mt][nt][2] + bs.x, v3 = of[mt][nt][3] + bs.y;
            if (n0 < 32) {
                uint32_t p0, p1;
                CVT_BF16X2(p0, v0 * qs, v1 * qs);
                CVT_BF16X2(p1, v2 * qs, v3 * qs);
                *reinterpret_cast<uint32_t*>(&g_Qb[((size_t)b * Ln + lq) * Dn + d])     = p0;
                *reinterpret_cast<uint32_t*>(&g_Qb[((size_t)b * Ln + lq + 8) * Dn + d]) = p1;
            } else if (n0 < 64) {
                int dk = d - 32;
                uint32_t p0, p1;
                CVT_BF16X2(p0, v0, v1);
                CVT_BF16X2(p1, v2, v3);
                *reinterpret_cast<uint32_t*>(&g_Kb[((size_t)b * Ln + lq) * Dn + dk])     = p0;
                *reinterpret_cast<uint32_t*>(&g_Kb[((size_t)b * Ln + lq + 8) * Dn + dk]) = p1;
            } else {
                int c = d - 64;
                vt[c * 136 + ll]           = __float2bfloat16(v0);
                vt[(c + 1) * 136 + ll]     = __float2bfloat16(v1);
                vt[c * 136 + ll + 8]       = __float2bfloat16(v2);
                vt[(c + 1) * 136 + ll + 8] = __float2bfloat16(v3);
            }
        }
    }
    __syncthreads();

    __nv_bfloat16* Vg = g_Vb + (size_t)b * Cn * Ln;
    for (int idx = t; idx < 256 * 16; idx += 512) {
        int c = idx >> 4, k8 = idx & 15;
        *reinterpret_cast<uint4*>(Vg + (size_t)c * Ln + l0 + k8 * 8) =
            *reinterpret_cast<const uint4*>(&vt[c * 136 + k8 * 8]);
    }
}

// ===========================================================================
// Kernel 2: HMMA flash attention (R14 structure) with split-PV barrier
// scheduling: PV(h = own jh) runs BEFORE the mid-chunk syncthreads using
// self-published P (thread-local ld-after-st, no barrier needed); the single
// mid syncthreads then both releases the K refill and guarantees the pair
// warp's P, after which PV(h = jh^1) runs.
// grid (L/128, 2, B) = 256 CTAs (one wave), 256 threads, 2 CTAs/SM.
// Smem: P slots 32768 | K 10240 | V 2x34816 = 112640.
// ===========================================================================
#define SM_P     0
#define SM_K     32768
#define SM_V(bi) (43008 + (bi) * 34816)
#define SM_TOTAL 112640

__global__ __launch_bounds__(256, 2) void attn_kernel(
    const float* __restrict__ x,
    const float* __restrict__ gamma,
    float* __restrict__ out)
{
    extern __shared__ __align__(16) char dsm[];
    const int b = blockIdx.z, ch_half = blockIdx.y, i0 = blockIdx.x * 128;
    const int t = threadIdx.x;
    const int w = t >> 5, lane = t & 31;
    const int qg = w >> 1, jh = w & 1;

    const uint32_t sbase = smem_to_u32(dsm);

    const __nv_bfloat16* Qg = &g_Qb[((size_t)b * Ln + i0) * Dn];
    const __nv_bfloat16* Kg = &g_Kb[(size_t)b * Ln * Dn];
    const __nv_bfloat16* Vg = &g_Vb[((size_t)b * Cn + ch_half * 128) * Ln];

    // prologue: chunk 0 loads
    {
        #pragma unroll
        for (int i = 0; i < 2; ++i) {
            int idx = t + i * 256;
            int j = idx >> 2, dc = idx & 3;
            cp_async16(sbase + SM_K + j * 80 + dc * 16, Kg + (size_t)j * Dn + dc * 8);
        }
        #pragma unroll
        for (int i = 0; i < 8; ++i) {
            int idx = t + i * 256;
            int c = idx >> 4, jc = idx & 15;
            cp_async16(sbase + SM_V(0) + c * 272 + jc * 16, Vg + (size_t)c * Ln + jc * 8);
        }
    }
    CP_COMMIT();

    // Q a-frags for both q-tiles, direct from global
    uint32_t aq[2][2][4];
    #pragma unroll
    for (int qt = 0; qt < 2; ++qt) {
        int row = qt * 64 + qg * 16 + (lane >> 2);
        const __nv_bfloat16* qr = Qg + (size_t)row * Dn + (lane & 3) * 2;
        #pragma unroll
        for (int ks = 0; ks < 2; ++ks) {
            aq[qt][ks][0] = *reinterpret_cast<const uint32_t*>(qr + ks * 16);
            aq[qt][ks][1] = *reinterpret_cast<const uint32_t*>(qr + 8 * Dn + ks * 16);
            aq[qt][ks][2] = *reinterpret_cast<const uint32_t*>(qr + ks * 16 + 8);
            aq[qt][ks][3] = *reinterpret_cast<const uint32_t*>(qr + 8 * Dn + ks * 16 + 8);
        }
    }

    const uint32_t kb_lane = (lane & 7) * 80 + ((lane >> 3) & 1) * 16;
    const uint32_t vb_lane = (uint32_t)(jh * 64) * 272 + (lane & 7) * 272 + (lane >> 3) * 16;
    const uint32_t slot_q0 = SM_P + (uint32_t)(((qg * 2 + 0) * 2 + jh) * 2048) + lane * 16;
    const uint32_t slot_q1 = slot_q0 + 4096;

    float of[2][8][4];
    #pragma unroll
    for (int qt = 0; qt < 2; ++qt)
        #pragma unroll
        for (int n = 0; n < 8; ++n)
            #pragma unroll
            for (int k = 0; k < 4; ++k) of[qt][n][k] = 0.f;
    float lsum[2][2] = {{0.f, 0.f}, {0.f, 0.f}};

#define QK_PHASE(QT, SLOT) do {                                                \
    uint32_t pa[4][4];                                                         \
    const uint32_t kh = ks_u + (uint32_t)(jh * 64) * 80 + kb_lane;             \
    _Pragma("unroll")                                                          \
    for (int jt = 0; jt < 8; ++jt) {                                           \
        float s0 = 0.f, s1 = 0.f, s2 = 0.f, s3 = 0.f;                          \
        uint32_t b0, b1;                                                       \
        uint32_t kaddr = kh + jt * 640;                                        \
        ldmatrix_x2(b0, b1, kaddr);                                            \
        mma_bf16(s0, s1, s2, s3, aq[QT][0][0], aq[QT][0][1],                   \
                 aq[QT][0][2], aq[QT][0][3], b0, b1);                          \
        ldmatrix_x2(b0, b1, kaddr + 32);                                       \
        mma_bf16(s0, s1, s2, s3, aq[QT][1][0], aq[QT][1][1],                   \
                 aq[QT][1][2], aq[QT][1][3], b0, b1);                          \
        float e0 = ex2f(s0), e1 = ex2f(s1), e2 = ex2f(s2), e3 = ex2f(s3);      \
        lsum[QT][0] += e0 + e1;                                                \
        lsum[QT][1] += e2 + e3;                                                \
        uint32_t plo, phi;                                                     \
        CVT_BF16X2(plo, e0, e1);                                               \
        CVT_BF16X2(phi, e2, e3);                                               \
        int pt = jt >> 1;                                                      \
        if ((jt & 1) == 0) { pa[pt][0] = plo; pa[pt][1] = phi; }               \
        else               { pa[pt][2] = plo; pa[pt][3] = phi; }               \
    }                                                                          \
    _Pragma("unroll")                                                          \
    for (int pt = 0; pt < 4; ++pt)                                             \
        *reinterpret_cast<uint4*>(dsm + (SLOT) + pt * 512) =                   \
            make_uint4(pa[pt][0], pa[pt][1], pa[pt][2], pa[pt][3]);            \
} while (0)

// PV for j-half H: reads P slots (qg, qt, H) for both q-tiles, V frags shared
#define PV_PHASE(H) do {                                                       \
    uint32_t p0[4][4], p1[4][4];                                               \
    const uint32_t rs0 = SM_P + (uint32_t)(((qg * 2 + 0) * 2 + (H)) * 2048)    \
                       + lane * 16;                                            \
    _Pragma("unroll")                                                          \
    for (int pt = 0; pt < 4; ++pt) {                                           \
        uint4 v = *reinterpret_cast<const uint4*>(dsm + rs0 + pt * 512);       \
        p0[pt][0] = v.x; p0[pt][1] = v.y; p0[pt][2] = v.z; p0[pt][3] = v.w;    \
        uint4 u = *reinterpret_cast<const uint4*>(dsm + rs0 + 4096 + pt * 512);\
        p1[pt][0] = u.x; p1[pt][1] = u.y; p1[pt][2] = u.z; p1[pt][3] = u.w;    \
    }                                                                          \
    _Pragma("unroll")                                                          \
    for (int nt = 0; nt < 8; ++nt) {                                           \
        uint32_t vbase = vs_u + (uint32_t)(nt * 8) * 272 + (H) * 128 + vb_lane;\
        uint32_t b0, b1, b2, b3;                                               \
        ldmatrix_x4(b0, b1, b2, b3, vbase);                                    \
        mma_bf16(of[0][nt][0], of[0][nt][1], of[0][nt][2], of[0][nt][3],       \
                 p0[0][0], p0[0][1], p0[0][2], p0[0][3], b0, b1);              \
        mma_bf16(of[1][nt][0], of[1][nt][1], of[1][nt][2], of[1][nt][3],       \
                 p1[0][0], p1[0][1], p1[0][2], p1[0][3], b0, b1);              \
        mma_bf16(of[0][nt][0], of[0][nt][1], of[0][nt][2], of[0][nt][3],       \
                 p0[1][0], p0[1][1], p0[1][2], p0[1][3], b2, b3);              \
        mma_bf16(of[1][nt][0], of[1][nt][1], of[1][nt][2], of[1][nt][3],       \
                 p1[1][0], p1[1][1], p1[1][2], p1[1][3], b2, b3);              \
        ldmatrix_x4(b0, b1, b2, b3, vbase + 64);                               \
        mma_bf16(of[0][nt][0], of[0][nt][1], of[0][nt][2], of[0][nt][3],       \
                 p0[2][0], p0[2][1], p0[2][2], p0[2][3], b0, b1);              \
        mma_bf16(of[1][nt][0], of[1][nt][1], of[1][nt][2], of[1][nt][3],       \
                 p1[2][0], p1[2][1], p1[2][2], p1[2][3], b0, b1);              \
        mma_bf16(of[0][nt][0], of[0][nt][1], of[0][nt][2], of[0][nt][3],       \
                 p0[3][0], p0[3][1], p0[3][2], p0[3][3], b2, b3);              \
        mma_bf16(of[1][nt][0], of[1][nt][1], of[1][nt][2], of[1][nt][3],       \
                 p1[3][0], p1[3][1], p1[3][2], p1[3][3], b2, b3);              \
    }                                                                          \
} while (0)

    const int NCHUNK = Ln / 128;
    for (int cidx = 0; cidx < NCHUNK; ++cidx) {
        CP_WAIT0();
        __syncthreads();   // K + V[bi] arrived; P slots and prev V buf free

        // issue next V chunk (double-buffered)
        if (cidx + 1 < NCHUNK) {
            int j0n = (cidx + 1) * 128;
            int bi = (cidx + 1) & 1;
            #pragma unroll
            for (int i = 0; i < 8; ++i) {
                int idx = t + i * 256;
                int c = idx >> 4, jc = idx & 15;
                cp_async16(sbase + SM_V(bi) + c * 272 + jc * 16,
                           Vg + (size_t)c * Ln + j0n + jc * 8);
            }
        }
        CP_COMMIT();

        const uint32_t ks_u = sbase + SM_K;
        const uint32_t vs_u = sbase + SM_V(cidx & 1);

        QK_PHASE(0, slot_q0);
        QK_PHASE(1, slot_q1);

        // PV own j-half: P was self-published by this lane (thread-local
        // ld-after-st to the same addresses) -> NO barrier needed.
        PV_PHASE(jh);

        __syncthreads();   // all K reads done; pair's P published

        // issue next K chunk into the single K buffer (hidden under PV below)
        if (cidx + 1 < NCHUNK) {
            int j0n = (cidx + 1) * 128;
            #pragma unroll
            for (int i = 0; i < 2; ++i) {
                int idx = t + i * 256;
                int j = idx >> 2, dc = idx & 3;
                cp_async16(sbase + SM_K + j * 80 + dc * 16,
                           Kg + (size_t)(j0n + j) * Dn + dc * 8);
            }
        }
        CP_COMMIT();

        // PV other j-half (pair warp's P)
        PV_PHASE(jh ^ 1);
    }

    // lsum: quad-reduce then combine across the jh pair (P region reused)
    __syncthreads();
    float l0s[2], l1s[2];
    #pragma unroll
    for (int qt = 0; qt < 2; ++qt) {
        float a = lsum[qt][0], c = lsum[qt][1];
        a += __shfl_xor_sync(0xFFFFFFFF, a, 1);
        a += __shfl_xor_sync(0xFFFFFFFF, a, 2);
        c += __shfl_xor_sync(0xFFFFFFFF, c, 1);
        c += __shfl_xor_sync(0xFFFFFFFF, c, 2);
        reinterpret_cast<float2*>(dsm + SM_P + (w * 2 + qt) * 256)[lane] = make_float2(a, c);
        l0s[qt] = a; l1s[qt] = c;
    }
    __syncthreads();
    #pragma unroll
    for (int qt = 0; qt < 2; ++qt) {
        float2 o = reinterpret_cast<const float2*>(
            dsm + SM_P + ((w ^ 1) * 2 + qt) * 256)[lane];
        l0s[qt] += o.x;
        l1s[qt] += o.y;
    }

    const float gam = __ldg(gamma);
    const float* xb = x + (size_t)b * Cn * Ln;
    float* ob = out + (size_t)b * Cn * Ln;
    float* Tsm = reinterpret_cast<float*>(dsm + SM_V(0));   // [128 ch][68 q] f32

    #pragma unroll
    for (int qt = 0; qt < 2; ++qt) {
        const float linv0 = 1.f / l0s[qt];
        const float linv1 = 1.f / l1s[qt];
        __syncthreads();
        {
            int q = qg * 16 + (lane >> 2);
            #pragma unroll
            for (int nt = 0; nt < 8; ++nt) {
                int cl = jh * 64 + nt * 8 + (lane & 3) * 2;
                Tsm[cl * 68 + q]           = of[qt][nt][0] * linv0;
                Tsm[(cl + 1) * 68 + q]     = of[qt][nt][1] * linv0;
                Tsm[cl * 68 + q + 8]       = of[qt][nt][2] * linv1;
                Tsm[(cl + 1) * 68 + q + 8] = of[qt][nt][3] * linv1;
            }
        }
        __syncthreads();
        for (int idx = t; idx < 128 * 64; idx += 256) {
            int cl = idx >> 6, qq = idx & 63;
            size_t off = (size_t)(ch_half * 128 + cl) * Ln + i0 + qt * 64 + qq;
            ob[off] = gam * Tsm[cl * 68 + qq] + xb[off];
        }
    }
}

// ===========================================================================
extern "C" void kernel_launch(void* const* d_in, const int* in_sizes, int n_in,
                              void* d_out, int out_size)
{
    const float* x     = (const float*)d_in[0];
    const float* Wq    = (const float*)d_in[1];
    const float* bq    = (const float*)d_in[2];
    const float* Wk    = (const float*)d_in[3];
    const float* bk    = (const float*)d_in[4];
    const float* Wv    = (const float*)d_in[5];
    const float* bv    = (const float*)d_in[6];
    const float* gamma = (const float*)d_in[7];
    float* out = (float*)d_out;

    cudaFuncSetAttribute(qkv_gemm, cudaFuncAttributeMaxDynamicSharedMemorySize, QKV_SMEM);
    cudaFuncSetAttribute(attn_kernel, cudaFuncAttributeMaxDynamicSharedMemorySize, SM_TOTAL);

    qkv_gemm<<<dim3(Ln / 128, Bn), 512, QKV_SMEM>>>(x, Wq, bq, Wk, bk, Wv, bv);
    attn_kernel<<<dim3(Ln / 128, 2, Bn), 256, SM_TOTAL>>>(x, gamma, out);
}

// round 16
// speedup vs baseline: 1.0503x; 1.0503x over previous
#include <cuda_runtime.h>
#include <cuda_bf16.h>
#include <cuda_fp16.h>
#include <cstdint>

#define Bn 8
#define Cn 256
#define Ln 2048
#define Dn 32

__device__ __nv_bfloat16 g_Qb[Bn * Ln * Dn];
__device__ __nv_bfloat16 g_Kb[Bn * Ln * Dn];
__device__ __nv_bfloat16 g_Vb[Bn * Cn * Ln];

__device__ __forceinline__ uint32_t smem_to_u32(const void* p) {
    uint32_t a;
    asm("{ .reg .u64 t; cvta.to.shared.u64 t, %1; cvt.u32.u64 %0, t; }" : "=r"(a) : "l"(p));
    return a;
}
__device__ __forceinline__ float ex2f(float x) {
    float r; asm("ex2.approx.ftz.f32 %0, %1;" : "=f"(r) : "f"(x)); return r;
}
#define CVT_BF16X2(res, a, b) \
    asm("cvt.rn.bf16x2.f32 %0, %1, %2;" : "=r"(res) : "f"(b), "f"(a))
#define CVT_F16X2(res, a, b) \
    asm("cvt.rn.f16x2.f32 %0, %1, %2;" : "=r"(res) : "f"(b), "f"(a))

__device__ __forceinline__ void ldmatrix_x4(uint32_t& r0, uint32_t& r1, uint32_t& r2, uint32_t& r3, uint32_t addr) {
    asm volatile("ldmatrix.sync.aligned.m8n8.x4.shared.b16 {%0,%1,%2,%3}, [%4];"
                 : "=r"(r0), "=r"(r1), "=r"(r2), "=r"(r3) : "r"(addr));
}
__device__ __forceinline__ void ldmatrix_x2(uint32_t& r0, uint32_t& r1, uint32_t addr) {
    asm volatile("ldmatrix.sync.aligned.m8n8.x2.shared.b16 {%0,%1}, [%2];"
                 : "=r"(r0), "=r"(r1) : "r"(addr));
}
__device__ __forceinline__ void mma_bf16(float& c0, float& c1, float& c2, float& c3,
                                         uint32_t a0, uint32_t a1, uint32_t a2, uint32_t a3,
                                         uint32_t b0, uint32_t b1) {
    asm volatile("mma.sync.aligned.m16n8k16.row.col.f32.bf16.bf16.f32 "
                 "{%0,%1,%2,%3}, {%4,%5,%6,%7}, {%8,%9}, {%0,%1,%2,%3};"
                 : "+f"(c0), "+f"(c1), "+f"(c2), "+f"(c3)
                 : "r"(a0), "r"(a1), "r"(a2), "r"(a3), "r"(b0), "r"(b1));
}
__device__ __forceinline__ void mma_fp16(float& c0, float& c1, float& c2, float& c3,
                                         uint32_t a0, uint32_t a1, uint32_t a2, uint32_t a3,
                                         uint32_t b0, uint32_t b1) {
    asm volatile("mma.sync.aligned.m16n8k16.row.col.f32.f16.f16.f32 "
                 "{%0,%1,%2,%3}, {%4,%5,%6,%7}, {%8,%9}, {%0,%1,%2,%3};"
                 : "+f"(c0), "+f"(c1), "+f"(c2), "+f"(c3)
                 : "r"(a0), "r"(a1), "r"(a2), "r"(a3), "r"(b0), "r"(b1));
}
__device__ __forceinline__ void cp_async16(uint32_t saddr, const void* gptr) {
    asm volatile("cp.async.cg.shared.global [%0], [%1], 16;" :: "r"(saddr), "l"(gptr));
}
#define CP_COMMIT() asm volatile("cp.async.commit_group;" ::: "memory")
#define CP_WAIT0()  asm volatile("cp.async.wait_group 0;" ::: "memory")

// ===========================================================================
// Kernel 1: QKV projection as HMMA GEMM (unchanged).
// ===========================================================================
#define QKV_SMEM 69632

__global__ __launch_bounds__(512) void qkv_gemm(
    const float* __restrict__ x,
    const float* __restrict__ Wq, const float* __restrict__ bq,
    const float* __restrict__ Wk, const float* __restrict__ bk,
    const float* __restrict__ Wv, const float* __restrict__ bv)
{
    extern __shared__ __align__(16) char qsmraw[];
    uint32_t* xs = reinterpret_cast<uint32_t*>(qsmraw);

    const int b = blockIdx.y, l0 = blockIdx.x * 128, t = threadIdx.x;
    const float* xb = x + (size_t)b * Cn * Ln;

    for (int idx = t; idx < 128 * 128; idx += 512) {
        int cp = idx >> 7, l = idx & 127;
        float f0 = xb[(size_t)(2 * cp) * Ln + l0 + l];
        float f1 = xb[(size_t)(2 * cp + 1) * Ln + l0 + l];
        uint32_t p; CVT_F16X2(p, f0, f1);
        xs[l * 132 + cp] = p;
    }
    __syncthreads();

    const int w = t >> 5, lane = t & 31;
    const int mg = w & 1, nh = w >> 1;
    const int nbase = nh * 40;

    const float* wp[5];
    #pragma unroll
    for (int nt = 0; nt < 5; ++nt) {
        int n0 = nbase + nt * 8;
        const float* src;
        if (n0 < 32)      src = Wq + n0 * Cn;
        else if (n0 < 64) src = Wk + (n0 - 32) * Cn;
        else              src = Wv + (n0 - 64) * Cn;
        wp[nt] = src + (lane >> 2) * Cn + (lane & 3) * 2;
    }

    float of[4][5][4];
    #pragma unroll
    for (int m = 0; m < 4; ++m)
        #pragma unroll
        for (int n = 0; n < 5; ++n)
            #pragma unroll
            for (int k = 0; k < 4; ++k) of[m][n][k] = 0.f;

    const uint32_t abase = smem_to_u32(xs)
        + (uint32_t)((mg * 64 + (lane & 15)) * 132) * 4 + ((lane >> 4) & 1) * 16;

    for (int ks = 0; ks < 16; ++ks) {
        uint32_t aq[4][4];
        #pragma unroll
        for (int mt = 0; mt < 4; ++mt)
            ldmatrix_x4(aq[mt][0], aq[mt][1], aq[mt][2], aq[mt][3],
                        abase + (uint32_t)(mt * 16 * 132) * 4 + ks * 32);
        #pragma unroll
        for (int nt = 0; nt < 5; ++nt) {
            float2 wa = __ldg(reinterpret_cast<const float2*>(wp[nt] + ks * 16));
            float2 wb = __ldg(reinterpret_cast<const float2*>(wp[nt] + ks * 16 + 8));
            uint32_t b0, b1;
            CVT_F16X2(b0, wa.x, wa.y);
            CVT_F16X2(b1, wb.x, wb.y);
            #pragma unroll
            for (int mt = 0; mt < 4; ++mt)
                mma_fp16(of[mt][nt][0], of[mt][nt][1], of[mt][nt][2], of[mt][nt][3],
                         aq[mt][0], aq[mt][1], aq[mt][2], aq[mt][3], b0, b1);
        }
    }
    __syncthreads();

    __nv_bfloat16* vt = reinterpret_cast<__nv_bfloat16*>(qsmraw);
    const float qs = 1.4426950408889634f * 0.17677669529663687f;

    #pragma unroll
    for (int nt = 0; nt < 5; ++nt) {
        int n0 = nbase + nt * 8;
        int d = n0 + (lane & 3) * 2;
        float2 bs;
        if (n0 < 32)      bs = __ldg(reinterpret_cast<const float2*>(bq + d));
        else if (n0 < 64) bs = __ldg(reinterpret_cast<const float2*>(bk + d - 32));
        else              bs = __ldg(reinterpret_cast<const float2*>(bv + d - 64));
        #pragma unroll
        for (int mt = 0; mt < 4; ++mt) {
            const int ll = mg * 64 + mt * 16 + (lane >> 2);
            const int lq = l0 + ll;
            float v0 = of[mt][nt][0] + bs.x, v1 = of[mt][nt][1] + bs.y;
            float v2 = of[mt][nt][2] + bs.x, v3 = of[mt][nt][3] + bs.y;
            if (n0 < 32) {
                uint32_t p0, p1;
                CVT_BF16X2(p0, v0 * qs, v1 * qs);
                CVT_BF16X2(p1, v2 * qs, v3 * qs);
                *reinterpret_cast<uint32_t*>(&g_Qb[((size_t)b * Ln + lq) * Dn + d])     = p0;
                *reinterpret_cast<uint32_t*>(&g_Qb[((size_t)b * Ln + lq + 8) * Dn + d]) = p1;
            } else if (n0 < 64) {
                int dk = d - 32;
                uint32_t p0, p1;
                CVT_BF16X2(p0, v0, v1);
                CVT_BF16X2(p1, v2, v3);
                *reinterpret_cast<uint32_t*>(&g_Kb[((size_t)b * Ln + lq) * Dn + dk])     = p0;
                *reinterpret_cast<uint32_t*>(&g_Kb[((size_t)b * Ln + lq + 8) * Dn + dk]) = p1;
            } else {
                int c = d - 64;
                vt[c * 136 + ll]           = __float2bfloat16(v0);
                vt[(c + 1) * 136 + ll]     = __float2bfloat16(v1);
                vt[c * 136 + ll + 8]       = __float2bfloat16(v2);
                vt[(c + 1) * 136 + ll + 8] = __float2bfloat16(v3);
            }
        }
    }
    __syncthreads();

    __nv_bfloat16* Vg = g_Vb + (size_t)b * Cn * Ln;
    for (int idx = t; idx < 256 * 16; idx += 512) {
        int c = idx >> 4, k8 = idx & 15;
        *reinterpret_cast<uint4*>(Vg + (size_t)c * Ln + l0 + k8 * 8) =
            *reinterpret_cast<const uint4*>(&vt[c * 136 + k8 * 8]);
    }
}

// ===========================================================================
// Kernel 2: HMMA flash attention (R14 structure) with FUSED QK phase:
// K fragments loaded once per jt and shared by both q-tiles (halves QK
// ldmatrix traffic, doubles QK-chain ILP). Barrier placement as in R14.
// grid (L/128, 2, B) = 256 CTAs (one wave), 256 threads, 2 CTAs/SM.
// Smem: P slots 32768 | K 10240 | V 2x34816 = 112640.
// ===========================================================================
#define SM_P     0
#define SM_K     32768
#define SM_V(bi) (43008 + (bi) * 34816)
#define SM_TOTAL 112640

__global__ __launch_bounds__(256, 2) void attn_kernel(
    const float* __restrict__ x,
    const float* __restrict__ gamma,
    float* __restrict__ out)
{
    extern __shared__ __align__(16) char dsm[];
    const int b = blockIdx.z, ch_half = blockIdx.y, i0 = blockIdx.x * 128;
    const int t = threadIdx.x;
    const int w = t >> 5, lane = t & 31;
    const int qg = w >> 1, jh = w & 1;

    const uint32_t sbase = smem_to_u32(dsm);

    const __nv_bfloat16* Qg = &g_Qb[((size_t)b * Ln + i0) * Dn];
    const __nv_bfloat16* Kg = &g_Kb[(size_t)b * Ln * Dn];
    const __nv_bfloat16* Vg = &g_Vb[((size_t)b * Cn + ch_half * 128) * Ln];

    // prologue: chunk 0 loads
    {
        #pragma unroll
        for (int i = 0; i < 2; ++i) {
            int idx = t + i * 256;
            int j = idx >> 2, dc = idx & 3;
            cp_async16(sbase + SM_K + j * 80 + dc * 16, Kg + (size_t)j * Dn + dc * 8);
        }
        #pragma unroll
        for (int i = 0; i < 8; ++i) {
            int idx = t + i * 256;
            int c = idx >> 4, jc = idx & 15;
            cp_async16(sbase + SM_V(0) + c * 272 + jc * 16, Vg + (size_t)c * Ln + jc * 8);
        }
    }
    CP_COMMIT();

    // Q a-frags for both q-tiles, direct from global
    uint32_t aq[2][2][4];
    #pragma unroll
    for (int qt = 0; qt < 2; ++qt) {
        int row = qt * 64 + qg * 16 + (lane >> 2);
        const __nv_bfloat16* qr = Qg + (size_t)row * Dn + (lane & 3) * 2;
        #pragma unroll
        for (int ks = 0; ks < 2; ++ks) {
            aq[qt][ks][0] = *reinterpret_cast<const uint32_t*>(qr + ks * 16);
            aq[qt][ks][1] = *reinterpret_cast<const uint32_t*>(qr + 8 * Dn + ks * 16);
            aq[qt][ks][2] = *reinterpret_cast<const uint32_t*>(qr + ks * 16 + 8);
            aq[qt][ks][3] = *reinterpret_cast<const uint32_t*>(qr + 8 * Dn + ks * 16 + 8);
        }
    }

    const uint32_t kb_lane = (lane & 7) * 80 + ((lane >> 3) & 1) * 16;
    const uint32_t vb_lane = (uint32_t)(jh * 64) * 272 + (lane & 7) * 272 + (lane >> 3) * 16;
    const uint32_t slot_q0 = SM_P + (uint32_t)(((qg * 2 + 0) * 2 + jh) * 2048) + lane * 16;
    const uint32_t slot_q1 = slot_q0 + 4096;

    float of[2][8][4];
    #pragma unroll
    for (int qt = 0; qt < 2; ++qt)
        #pragma unroll
        for (int n = 0; n < 8; ++n)
            #pragma unroll
            for (int k = 0; k < 4; ++k) of[qt][n][k] = 0.f;
    float lsum[2][2] = {{0.f, 0.f}, {0.f, 0.f}};

    const int NCHUNK = Ln / 128;
    for (int cidx = 0; cidx < NCHUNK; ++cidx) {
        CP_WAIT0();
        __syncthreads();   // K + V[bi] arrived; P slots and prev V buf free

        // issue next V chunk (double-buffered)
        if (cidx + 1 < NCHUNK) {
            int j0n = (cidx + 1) * 128;
            int bi = (cidx + 1) & 1;
            #pragma unroll
            for (int i = 0; i < 8; ++i) {
                int idx = t + i * 256;
                int c = idx >> 4, jc = idx & 15;
                cp_async16(sbase + SM_V(bi) + c * 272 + jc * 16,
                           Vg + (size_t)c * Ln + j0n + jc * 8);
            }
        }
        CP_COMMIT();

        const uint32_t ks_u = sbase + SM_K;
        const uint32_t vs_u = sbase + SM_V(cidx & 1);

        // FUSED QK phase: K frags loaded once, shared by both q-tiles.
        {
            uint32_t pa0[4][4], pa1[4][4];
            const uint32_t kh = ks_u + (uint32_t)(jh * 64) * 80 + kb_lane;
            #pragma unroll
            for (int jt = 0; jt < 8; ++jt) {
                uint32_t b0, b1, b2, b3;
                uint32_t kaddr = kh + jt * 640;
                ldmatrix_x2(b0, b1, kaddr);
                ldmatrix_x2(b2, b3, kaddr + 32);

                float s0 = 0.f, s1 = 0.f, s2 = 0.f, s3 = 0.f;   // qt0
                float r0 = 0.f, r1 = 0.f, r2 = 0.f, r3 = 0.f;   // qt1
                mma_bf16(s0, s1, s2, s3, aq[0][0][0], aq[0][0][1],
                         aq[0][0][2], aq[0][0][3], b0, b1);
                mma_bf16(r0, r1, r2, r3, aq[1][0][0], aq[1][0][1],
                         aq[1][0][2], aq[1][0][3], b0, b1);
                mma_bf16(s0, s1, s2, s3, aq[0][1][0], aq[0][1][1],
                         aq[0][1][2], aq[0][1][3], b2, b3);
                mma_bf16(r0, r1, r2, r3, aq[1][1][0], aq[1][1][1],
                         aq[1][1][2], aq[1][1][3], b2, b3);

                float e0 = ex2f(s0), e1 = ex2f(s1), e2 = ex2f(s2), e3 = ex2f(s3);
                float f0 = ex2f(r0), f1 = ex2f(r1), f2 = ex2f(r2), f3 = ex2f(r3);
                lsum[0][0] += e0 + e1;
                lsum[0][1] += e2 + e3;
                lsum[1][0] += f0 + f1;
                lsum[1][1] += f2 + f3;
                uint32_t plo, phi, qlo, qhi;
                CVT_BF16X2(plo, e0, e1);
                CVT_BF16X2(phi, e2, e3);
                CVT_BF16X2(qlo, f0, f1);
                CVT_BF16X2(qhi, f2, f3);
                int pt = jt >> 1;
                if ((jt & 1) == 0) {
                    pa0[pt][0] = plo; pa0[pt][1] = phi;
                    pa1[pt][0] = qlo; pa1[pt][1] = qhi;
                } else {
                    pa0[pt][2] = plo; pa0[pt][3] = phi;
                    pa1[pt][2] = qlo; pa1[pt][3] = qhi;
                }
            }
            #pragma unroll
            for (int pt = 0; pt < 4; ++pt) {
                *reinterpret_cast<uint4*>(dsm + slot_q0 + pt * 512) =
                    make_uint4(pa0[pt][0], pa0[pt][1], pa0[pt][2], pa0[pt][3]);
                *reinterpret_cast<uint4*>(dsm + slot_q1 + pt * 512) =
                    make_uint4(pa1[pt][0], pa1[pt][1], pa1[pt][2], pa1[pt][3]);
            }
        }
        __syncthreads();   // K reads done; all P published

        // issue next K chunk into the single K buffer (hidden under PV)
        if (cidx + 1 < NCHUNK) {
            int j0n = (cidx + 1) * 128;
            #pragma unroll
            for (int i = 0; i < 2; ++i) {
                int idx = t + i * 256;
                int j = idx >> 2, dc = idx & 3;
                cp_async16(sbase + SM_K + j * 80 + dc * 16,
                           Kg + (size_t)(j0n + j) * Dn + dc * 8);
            }
        }
        CP_COMMIT();

        // PV: h-outer, nt-inner; V fragments shared by both q-tiles.
        #pragma unroll
        for (int h = 0; h < 2; ++h) {
            uint32_t p0[4][4], p1[4][4];
            const uint32_t rs0 = SM_P + (uint32_t)(((qg * 2 + 0) * 2 + h) * 2048) + lane * 16;
            #pragma unroll
            for (int pt = 0; pt < 4; ++pt) {
                uint4 v = *reinterpret_cast<const uint4*>(dsm + rs0 + pt * 512);
                p0[pt][0] = v.x; p0[pt][1] = v.y; p0[pt][2] = v.z; p0[pt][3] = v.w;
                uint4 u = *reinterpret_cast<const uint4*>(dsm + rs0 + 4096 + pt * 512);
                p1[pt][0] = u.x; p1[pt][1] = u.y; p1[pt][2] = u.z; p1[pt][3] = u.w;
            }
            #pragma unroll
            for (int nt = 0; nt < 8; ++nt) {
                uint32_t vbase = vs_u + (uint32_t)(nt * 8) * 272 + h * 128 + vb_lane;
                uint32_t b0, b1, b2, b3;
                ldmatrix_x4(b0, b1, b2, b3, vbase);
                mma_bf16(of[0][nt][0], of[0][nt][1], of[0][nt][2], of[0][nt][3],
                         p0[0][0], p0[0][1], p0[0][2], p0[0][3], b0, b1);
                mma_bf16(of[1][nt][0], of[1][nt][1], of[1][nt][2], of[1][nt][3],
                         p1[0][0], p1[0][1], p1[0][2], p1[0][3], b0, b1);
                mma_bf16(of[0][nt][0], of[0][nt][1], of[0][nt][2], of[0][nt][3],
                         p0[1][0], p0[1][1], p0[1][2], p0[1][3], b2, b3);
                mma_bf16(of[1][nt][0], of[1][nt][1], of[1][nt][2], of[1][nt][3],
                         p1[1][0], p1[1][1], p1[1][2], p1[1][3], b2, b3);
                ldmatrix_x4(b0, b1, b2, b3, vbase + 64);
                mma_bf16(of[0][nt][0], of[0][nt][1], of[0][nt][2], of[0][nt][3],
                         p0[2][0], p0[2][1], p0[2][2], p0[2][3], b0, b1);
                mma_bf16(of[1][nt][0], of[1][nt][1], of[1][nt][2], of[1][nt][3],
                         p1[2][0], p1[2][1], p1[2][2], p1[2][3], b0, b1);
                mma_bf16(of[0][nt][0], of[0][nt][1], of[0][nt][2], of[0][nt][3],
                         p0[3][0], p0[3][1], p0[3][2], p0[3][3], b2, b3);
                mma_bf16(of[1][nt][0], of[1][nt][1], of[1][nt][2], of[1][nt][3],
                         p1[3][0], p1[3][1], p1[3][2], p1[3][3], b2, b3);
            }
        }
    }

    // lsum: quad-reduce then combine across the jh pair (P region reused)
    __syncthreads();
    float l0s[2], l1s[2];
    #pragma unroll
    for (int qt = 0; qt < 2; ++qt) {
        float a = lsum[qt][0], c = lsum[qt][1];
        a += __shfl_xor_sync(0xFFFFFFFF, a, 1);
        a += __shfl_xor_sync(0xFFFFFFFF, a, 2);
        c += __shfl_xor_sync(0xFFFFFFFF, c, 1);
        c += __shfl_xor_sync(0xFFFFFFFF, c, 2);
        reinterpret_cast<float2*>(dsm + SM_P + (w * 2 + qt) * 256)[lane] = make_float2(a, c);
        l0s[qt] = a; l1s[qt] = c;
    }
    __syncthreads();
    #pragma unroll
    for (int qt = 0; qt < 2; ++qt) {
        float2 o = reinterpret_cast<const float2*>(
            dsm + SM_P + ((w ^ 1) * 2 + qt) * 256)[lane];
        l0s[qt] += o.x;
        l1s[qt] += o.y;
    }

    const float gam = __ldg(gamma);
    const float* xb = x + (size_t)b * Cn * Ln;
    float* ob = out + (size_t)b * Cn * Ln;
    float* Tsm = reinterpret_cast<float*>(dsm + SM_V(0));   // [128 ch][68 q] f32

    #pragma unroll
    for (int qt = 0; qt < 2; ++qt) {
        const float linv0 = 1.f / l0s[qt];
        const float linv1 = 1.f / l1s[qt];
        __syncthreads();
        {
            int q = qg * 16 + (lane >> 2);
            #pragma unroll
            for (int nt = 0; nt < 8; ++nt) {
                int cl = jh * 64 + nt * 8 + (lane & 3) * 2;
                Tsm[cl * 68 + q]           = of[qt][nt][0] * linv0;
                Tsm[(cl + 1) * 68 + q]     = of[qt][nt][1] * linv0;
                Tsm[cl * 68 + q + 8]       = of[qt][nt][2] * linv1;
                Tsm[(cl + 1) * 68 + q + 8] = of[qt][nt][3] * linv1;
            }
        }
        __syncthreads();
        for (int idx = t; idx < 128 * 64; idx += 256) {
            int cl = idx >> 6, qq = idx & 63;
            size_t off = (size_t)(ch_half * 128 + cl) * Ln + i0 + qt * 64 + qq;
            ob[off] = gam * Tsm[cl * 68 + qq] + xb[off];
        }
    }
}

// ===========================================================================
extern "C" void kernel_launch(void* const* d_in, const int* in_sizes, int n_in,
                              void* d_out, int out_size)
{
    const float* x     = (const float*)d_in[0];
    const float* Wq    = (const float*)d_in[1];
    const float* bq    = (const float*)d_in[2];
    const float* Wk    = (const float*)d_in[3];
    const float* bk    = (const float*)d_in[4];
    const float* Wv    = (const float*)d_in[5];
    const float* bv    = (const float*)d_in[6];
    const float* gamma = (const float*)d_in[7];
    float* out = (float*)d_out;

    cudaFuncSetAttribute(qkv_gemm, cudaFuncAttributeMaxDynamicSharedMemorySize, QKV_SMEM);
    cudaFuncSetAttribute(attn_kernel, cudaFuncAttributeMaxDynamicSharedMemorySize, SM_TOTAL);

    qkv_gemm<<<dim3(Ln / 128, Bn), 512, QKV_SMEM>>>(x, Wq, bq, Wk, bk, Wv, bv);
    attn_kernel<<<dim3(Ln / 128, 2, Bn), 256, SM_TOTAL>>>(x, gamma, out);
}

// round 17
// speedup vs baseline: 1.0642x; 1.0132x over previous
#include <cuda_runtime.h>
#include <cuda_bf16.h>
#include <cuda_fp16.h>
#include <cstdint>

#define Bn 8
#define Cn 256
#define Ln 2048
#define Dn 32

__device__ __nv_bfloat16 g_Qb[Bn * Ln * Dn];   // [b][l][d] pre-scaled by scale*log2e
__device__ __nv_bfloat16 g_Kb[Bn * Ln * Dn];   // [b][l][d]
__device__ __half        g_Vh[Bn * Cn * Ln];   // [b][c][l] fp16

__device__ __forceinline__ uint32_t smem_to_u32(const void* p) {
    uint32_t a;
    asm("{ .reg .u64 t; cvta.to.shared.u64 t, %1; cvt.u32.u64 %0, t; }" : "=r"(a) : "l"(p));
    return a;
}
#define CVT_BF16X2(res, a, b) \
    asm("cvt.rn.bf16x2.f32 %0, %1, %2;" : "=r"(res) : "f"(b), "f"(a))
#define CVT_F16X2(res, a, b) \
    asm("cvt.rn.f16x2.f32 %0, %1, %2;" : "=r"(res) : "f"(b), "f"(a))
// packed fp16 2^x on MUFU (halves exp op count)
#define EX2X2(res, a) \
    asm("ex2.approx.f16x2 %0, %1;" : "=r"(res) : "r"(a))
#define HADD2(res, a, b) \
    asm("add.rn.f16x2 %0, %1, %2;" : "=r"(res) : "r"(a), "r"(b))

__device__ __forceinline__ void ldmatrix_x4(uint32_t& r0, uint32_t& r1, uint32_t& r2, uint32_t& r3, uint32_t addr) {
    asm volatile("ldmatrix.sync.aligned.m8n8.x4.shared.b16 {%0,%1,%2,%3}, [%4];"
                 : "=r"(r0), "=r"(r1), "=r"(r2), "=r"(r3) : "r"(addr));
}
__device__ __forceinline__ void ldmatrix_x2(uint32_t& r0, uint32_t& r1, uint32_t addr) {
    asm volatile("ldmatrix.sync.aligned.m8n8.x2.shared.b16 {%0,%1}, [%2];"
                 : "=r"(r0), "=r"(r1) : "r"(addr));
}
__device__ __forceinline__ void mma_bf16(float& c0, float& c1, float& c2, float& c3,
                                         uint32_t a0, uint32_t a1, uint32_t a2, uint32_t a3,
                                         uint32_t b0, uint32_t b1) {
    asm volatile("mma.sync.aligned.m16n8k16.row.col.f32.bf16.bf16.f32 "
                 "{%0,%1,%2,%3}, {%4,%5,%6,%7}, {%8,%9}, {%0,%1,%2,%3};"
                 : "+f"(c0), "+f"(c1), "+f"(c2), "+f"(c3)
                 : "r"(a0), "r"(a1), "r"(a2), "r"(a3), "r"(b0), "r"(b1));
}
__device__ __forceinline__ void mma_fp16(float& c0, float& c1, float& c2, float& c3,
                                         uint32_t a0, uint32_t a1, uint32_t a2, uint32_t a3,
                                         uint32_t b0, uint32_t b1) {
    asm volatile("mma.sync.aligned.m16n8k16.row.col.f32.f16.f16.f32 "
                 "{%0,%1,%2,%3}, {%4,%5,%6,%7}, {%8,%9}, {%0,%1,%2,%3};"
                 : "+f"(c0), "+f"(c1), "+f"(c2), "+f"(c3)
                 : "r"(a0), "r"(a1), "r"(a2), "r"(a3), "r"(b0), "r"(b1));
}
__device__ __forceinline__ void cp_async16(uint32_t saddr, const void* gptr) {
    asm volatile("cp.async.cg.shared.global [%0], [%1], 16;" :: "r"(saddr), "l"(gptr));
}
#define CP_COMMIT() asm volatile("cp.async.commit_group;" ::: "memory")
#define CP_WAIT0()  asm volatile("cp.async.wait_group 0;" ::: "memory")

// ===========================================================================
// Kernel 1: QKV projection as HMMA GEMM (V now written fp16).
// grid (L/128, B), 512 threads.
// ===========================================================================
#define QKV_SMEM 69632

__global__ __launch_bounds__(512) void qkv_gemm(
    const float* __restrict__ x,
    const float* __restrict__ Wq, const float* __restrict__ bq,
    const float* __restrict__ Wk, const float* __restrict__ bk,
    const float* __restrict__ Wv, const float* __restrict__ bv)
{
    extern __shared__ __align__(16) char qsmraw[];
    uint32_t* xs = reinterpret_cast<uint32_t*>(qsmraw);

    const int b = blockIdx.y, l0 = blockIdx.x * 128, t = threadIdx.x;
    const float* xb = x + (size_t)b * Cn * Ln;

    for (int idx = t; idx < 128 * 128; idx += 512) {
        int cp = idx >> 7, l = idx & 127;
        float f0 = xb[(size_t)(2 * cp) * Ln + l0 + l];
        float f1 = xb[(size_t)(2 * cp + 1) * Ln + l0 + l];
        uint32_t p; CVT_F16X2(p, f0, f1);
        xs[l * 132 + cp] = p;
    }
    __syncthreads();

    const int w = t >> 5, lane = t & 31;
    const int mg = w & 1, nh = w >> 1;
    const int nbase = nh * 40;

    const float* wp[5];
    #pragma unroll
    for (int nt = 0; nt < 5; ++nt) {
        int n0 = nbase + nt * 8;
        const float* src;
        if (n0 < 32)      src = Wq + n0 * Cn;
        else if (n0 < 64) src = Wk + (n0 - 32) * Cn;
        else              src = Wv + (n0 - 64) * Cn;
        wp[nt] = src + (lane >> 2) * Cn + (lane & 3) * 2;
    }

    float of[4][5][4];
    #pragma unroll
    for (int m = 0; m < 4; ++m)
        #pragma unroll
        for (int n = 0; n < 5; ++n)
            #pragma unroll
            for (int k = 0; k < 4; ++k) of[m][n][k] = 0.f;

    const uint32_t abase = smem_to_u32(xs)
        + (uint32_t)((mg * 64 + (lane & 15)) * 132) * 4 + ((lane >> 4) & 1) * 16;

    for (int ks = 0; ks < 16; ++ks) {
        uint32_t aq[4][4];
        #pragma unroll
        for (int mt = 0; mt < 4; ++mt)
            ldmatrix_x4(aq[mt][0], aq[mt][1], aq[mt][2], aq[mt][3],
                        abase + (uint32_t)(mt * 16 * 132) * 4 + ks * 32);
        #pragma unroll
        for (int nt = 0; nt < 5; ++nt) {
            float2 wa = __ldg(reinterpret_cast<const float2*>(wp[nt] + ks * 16));
            float2 wb = __ldg(reinterpret_cast<const float2*>(wp[nt] + ks * 16 + 8));
            uint32_t b0, b1;
            CVT_F16X2(b0, wa.x, wa.y);
            CVT_F16X2(b1, wb.x, wb.y);
            #pragma unroll
            for (int mt = 0; mt < 4; ++mt)
                mma_fp16(of[mt][nt][0], of[mt][nt][1], of[mt][nt][2], of[mt][nt][3],
                         aq[mt][0], aq[mt][1], aq[mt][2], aq[mt][3], b0, b1);
        }
    }
    __syncthreads();

    __half* vt = reinterpret_cast<__half*>(qsmraw);   // [256][136] fp16
    const float qs = 1.4426950408889634f * 0.17677669529663687f;

    #pragma unroll
    for (int nt = 0; nt < 5; ++nt) {
        int n0 = nbase + nt * 8;
        int d = n0 + (lane & 3) * 2;
        float2 bs;
        if (n0 < 32)      bs = __ldg(reinterpret_cast<const float2*>(bq + d));
        else if (n0 < 64) bs = __ldg(reinterpret_cast<const float2*>(bk + d - 32));
        else              bs = __ldg(reinterpret_cast<const float2*>(bv + d - 64));
        #pragma unroll
        for (int mt = 0; mt < 4; ++mt) {
            const int ll = mg * 64 + mt * 16 + (lane >> 2);
            const int lq = l0 + ll;
            float v0 = of[mt][nt][0] + bs.x, v1 = of[mt][nt][1] + bs.y;
            float v2 = of[mt][nt][2] + bs.x, v3 = of[mt][nt][3] + bs.y;
            if (n0 < 32) {
                uint32_t p0, p1;
                CVT_BF16X2(p0, v0 * qs, v1 * qs);
                CVT_BF16X2(p1, v2 * qs, v3 * qs);
                *reinterpret_cast<uint32_t*>(&g_Qb[((size_t)b * Ln + lq) * Dn + d])     = p0;
                *reinterpret_cast<uint32_t*>(&g_Qb[((size_t)b * Ln + lq + 8) * Dn + d]) = p1;
            } else if (n0 < 64) {
                int dk = d - 32;
                uint32_t p0, p1;
                CVT_BF16X2(p0, v0, v1);
                CVT_BF16X2(p1, v2, v3);
                *reinterpret_cast<uint32_t*>(&g_Kb[((size_t)b * Ln + lq) * Dn + dk])     = p0;
                *reinterpret_cast<uint32_t*>(&g_Kb[((size_t)b * Ln + lq + 8) * Dn + dk]) = p1;
            } else {
                int c = d - 64;
                vt[c * 136 + ll]           = __float2half(v0);
                vt[(c + 1) * 136 + ll]     = __float2half(v1);
                vt[c * 136 + ll + 8]       = __float2half(v2);
                vt[(c + 1) * 136 + ll + 8] = __float2half(v3);
            }
        }
    }
    __syncthreads();

    __half* Vg = g_Vh + (size_t)b * Cn * Ln;
    for (int idx = t; idx < 256 * 16; idx += 512) {
        int c = idx >> 4, k8 = idx & 15;
        *reinterpret_cast<uint4*>(Vg + (size_t)c * Ln + l0 + k8 * 8) =
            *reinterpret_cast<const uint4*>(&vt[c * 136 + k8 * 8]);
    }
}

// ===========================================================================
// Kernel 2: HMMA flash attention (R16 structure). QK bf16, exp via packed
// ex2.approx.f16x2 (MUFU halved), P and V fp16, PV fp16 HMMA. Row-sums
// accumulated packed fp16 within a chunk, widened to fp32 per chunk.
// grid (L/128, 2, B) = 256 CTAs (one wave), 256 threads, 2 CTAs/SM.
// Smem: P slots 32768 | K 10240 | V 2x34816 = 112640.
// ===========================================================================
#define SM_P     0
#define SM_K     32768
#define SM_V(bi) (43008 + (bi) * 34816)
#define SM_TOTAL 112640

__global__ __launch_bounds__(256, 2) void attn_kernel(
    const float* __restrict__ x,
    const float* __restrict__ gamma,
    float* __restrict__ out)
{
    extern __shared__ __align__(16) char dsm[];
    const int b = blockIdx.z, ch_half = blockIdx.y, i0 = blockIdx.x * 128;
    const int t = threadIdx.x;
    const int w = t >> 5, lane = t & 31;
    const int qg = w >> 1, jh = w & 1;

    const uint32_t sbase = smem_to_u32(dsm);

    const __nv_bfloat16* Qg = &g_Qb[((size_t)b * Ln + i0) * Dn];
    const __nv_bfloat16* Kg = &g_Kb[(size_t)b * Ln * Dn];
    const __half* Vg = &g_Vh[((size_t)b * Cn + ch_half * 128) * Ln];

    // prologue: chunk 0 loads
    {
        #pragma unroll
        for (int i = 0; i < 2; ++i) {
            int idx = t + i * 256;
            int j = idx >> 2, dc = idx & 3;
            cp_async16(sbase + SM_K + j * 80 + dc * 16, Kg + (size_t)j * Dn + dc * 8);
        }
        #pragma unroll
        for (int i = 0; i < 8; ++i) {
            int idx = t + i * 256;
            int c = idx >> 4, jc = idx & 15;
            cp_async16(sbase + SM_V(0) + c * 272 + jc * 16, Vg + (size_t)c * Ln + jc * 8);
        }
    }
    CP_COMMIT();

    // Q a-frags for both q-tiles, direct from global
    uint32_t aq[2][2][4];
    #pragma unroll
    for (int qt = 0; qt < 2; ++qt) {
        int row = qt * 64 + qg * 16 + (lane >> 2);
        const __nv_bfloat16* qr = Qg + (size_t)row * Dn + (lane & 3) * 2;
        #pragma unroll
        for (int ks = 0; ks < 2; ++ks) {
            aq[qt][ks][0] = *reinterpret_cast<const uint32_t*>(qr + ks * 16);
            aq[qt][ks][1] = *reinterpret_cast<const uint32_t*>(qr + 8 * Dn + ks * 16);
            aq[qt][ks][2] = *reinterpret_cast<const uint32_t*>(qr + ks * 16 + 8);
            aq[qt][ks][3] = *reinterpret_cast<const uint32_t*>(qr + 8 * Dn + ks * 16 + 8);
        }
    }

    const uint32_t kb_lane = (lane & 7) * 80 + ((lane >> 3) & 1) * 16;
    const uint32_t vb_lane = (uint32_t)(jh * 64) * 272 + (lane & 7) * 272 + (lane >> 3) * 16;
    const uint32_t slot_q0 = SM_P + (uint32_t)(((qg * 2 + 0) * 2 + jh) * 2048) + lane * 16;
    const uint32_t slot_q1 = slot_q0 + 4096;

    float of[2][8][4];
    #pragma unroll
    for (int qt = 0; qt < 2; ++qt)
        #pragma unroll
        for (int n = 0; n < 8; ++n)
            #pragma unroll
            for (int k = 0; k < 4; ++k) of[qt][n][k] = 0.f;
    float lsum[2][2] = {{0.f, 0.f}, {0.f, 0.f}};

    const int NCHUNK = Ln / 128;
    for (int cidx = 0; cidx < NCHUNK; ++cidx) {
        CP_WAIT0();
        __syncthreads();   // K + V[bi] arrived; P slots and prev V buf free

        // issue next V chunk (double-buffered)
        if (cidx + 1 < NCHUNK) {
            int j0n = (cidx + 1) * 128;
            int bi = (cidx + 1) & 1;
            #pragma unroll
            for (int i = 0; i < 8; ++i) {
                int idx = t + i * 256;
                int c = idx >> 4, jc = idx & 15;
                cp_async16(sbase + SM_V(bi) + c * 272 + jc * 16,
                           Vg + (size_t)c * Ln + j0n + jc * 8);
            }
        }
        CP_COMMIT();

        const uint32_t ks_u = sbase + SM_K;
        const uint32_t vs_u = sbase + SM_V(cidx & 1);

        // FUSED QK phase: K frags shared by both q-tiles; exp packed fp16x2.
        {
            uint32_t pa0[4][4], pa1[4][4];
            uint32_t la00 = 0, la01 = 0, la10 = 0, la11 = 0;   // f16x2 row-sum accs
            const uint32_t kh = ks_u + (uint32_t)(jh * 64) * 80 + kb_lane;
            #pragma unroll
            for (int jt = 0; jt < 8; ++jt) {
                uint32_t b0, b1, b2, b3;
                uint32_t kaddr = kh + jt * 640;
                ldmatrix_x2(b0, b1, kaddr);
                ldmatrix_x2(b2, b3, kaddr + 32);

                float s0 = 0.f, s1 = 0.f, s2 = 0.f, s3 = 0.f;   // qt0
                float r0 = 0.f, r1 = 0.f, r2 = 0.f, r3 = 0.f;   // qt1
                mma_bf16(s0, s1, s2, s3, aq[0][0][0], aq[0][0][1],
                         aq[0][0][2], aq[0][0][3], b0, b1);
                mma_bf16(r0, r1, r2, r3, aq[1][0][0], aq[1][0][1],
                         aq[1][0][2], aq[1][0][3], b0, b1);
                mma_bf16(s0, s1, s2, s3, aq[0][1][0], aq[0][1][1],
                         aq[0][1][2], aq[0][1][3], b2, b3);
                mma_bf16(r0, r1, r2, r3, aq[1][1][0], aq[1][1][1],
                         aq[1][1][2], aq[1][1][3], b2, b3);

                uint32_t u01, u23, v01, v23;
                CVT_F16X2(u01, s0, s1);
                CVT_F16X2(u23, s2, s3);
                CVT_F16X2(v01, r0, r1);
                CVT_F16X2(v23, r2, r3);
                uint32_t p01, p23, q01, q23;
                EX2X2(p01, u01);
                EX2X2(p23, u23);
                EX2X2(q01, v01);
                EX2X2(q23, v23);
                HADD2(la00, la00, p01);
                HADD2(la01, la01, p23);
                HADD2(la10, la10, q01);
                HADD2(la11, la11, q23);
                int pt = jt >> 1;
                if ((jt & 1) == 0) {
                    pa0[pt][0] = p01; pa0[pt][1] = p23;
                    pa1[pt][0] = q01; pa1[pt][1] = q23;
                } else {
                    pa0[pt][2] = p01; pa0[pt][3] = p23;
                    pa1[pt][2] = q01; pa1[pt][3] = q23;
                }
            }
            #pragma unroll
            for (int pt = 0; pt < 4; ++pt) {
                *reinterpret_cast<uint4*>(dsm + slot_q0 + pt * 512) =
                    make_uint4(pa0[pt][0], pa0[pt][1], pa0[pt][2], pa0[pt][3]);
                *reinterpret_cast<uint4*>(dsm + slot_q1 + pt * 512) =
                    make_uint4(pa1[pt][0], pa1[pt][1], pa1[pt][2], pa1[pt][3]);
            }
            // widen packed row-sums to fp32 (once per chunk)
            float2 f;
            f = __half22float2(*reinterpret_cast<__half2*>(&la00)); lsum[0][0] += f.x + f.y;
            f = __half22float2(*reinterpret_cast<__half2*>(&la01)); lsum[0][1] += f.x + f.y;
            f = __half22float2(*reinterpret_cast<__half2*>(&la10)); lsum[1][0] += f.x + f.y;
            f = __half22float2(*reinterpret_cast<__half2*>(&la11)); lsum[1][1] += f.x + f.y;
        }
        __syncthreads();   // K reads done; all P published

        // issue next K chunk into the single K buffer (hidden under PV)
        if (cidx + 1 < NCHUNK) {
            int j0n = (cidx + 1) * 128;
            #pragma unroll
            for (int i = 0; i < 2; ++i) {
                int idx = t + i * 256;
                int j = idx >> 2, dc = idx & 3;
                cp_async16(sbase + SM_K + j * 80 + dc * 16,
                           Kg + (size_t)(j0n + j) * Dn + dc * 8);
            }
        }
        CP_COMMIT();

        // PV (fp16): h-outer, nt-inner; V fragments shared by both q-tiles.
        #pragma unroll
        for (int h = 0; h < 2; ++h) {
            uint32_t p0[4][4], p1[4][4];
            const uint32_t rs0 = SM_P + (uint32_t)(((qg * 2 + 0) * 2 + h) * 2048) + lane * 16;
            #pragma unroll
            for (int pt = 0; pt < 4; ++pt) {
                uint4 v = *reinterpret_cast<const uint4*>(dsm + rs0 + pt * 512);
                p0[pt][0] = v.x; p0[pt][1] = v.y; p0[pt][2] = v.z; p0[pt][3] = v.w;
                uint4 u = *reinterpret_cast<const uint4*>(dsm + rs0 + 4096 + pt * 512);
                p1[pt][0] = u.x; p1[pt][1] = u.y; p1[pt][2] = u.z; p1[pt][3] = u.w;
            }
            #pragma unroll
            for (int nt = 0; nt < 8; ++nt) {
                uint32_t vbase = vs_u + (uint32_t)(nt * 8) * 272 + h * 128 + vb_lane;
                uint32_t b0, b1, b2, b3;
                ldmatrix_x4(b0, b1, b2, b3, vbase);
                mma_fp16(of[0][nt][0], of[0][nt][1], of[0][nt][2], of[0][nt][3],
                         p0[0][0], p0[0][1], p0[0][2], p0[0][3], b0, b1);
                mma_fp16(of[1][nt][0], of[1][nt][1], of[1][nt][2], of[1][nt][3],
                         p1[0][0], p1[0][1], p1[0][2], p1[0][3], b0, b1);
                mma_fp16(of[0][nt][0], of[0][nt][1], of[0][nt][2], of[0][nt][3],
                         p0[1][0], p0[1][1], p0[1][2], p0[1][3], b2, b3);
                mma_fp16(of[1][nt][0], of[1][nt][1], of[1][nt][2], of[1][nt][3],
                         p1[1][0], p1[1][1], p1[1][2], p1[1][3], b2, b3);
                ldmatrix_x4(b0, b1, b2, b3, vbase + 64);
                mma_fp16(of[0][nt][0], of[0][nt][1], of[0][nt][2], of[0][nt][3],
                         p0[2][0], p0[2][1], p0[2][2], p0[2][3], b0, b1);
                mma_fp16(of[1][nt][0], of[1][nt][1], of[1][nt][2], of[1][nt][3],
                         p1[2][0], p1[2][1], p1[2][2], p1[2][3], b0, b1);
                mma_fp16(of[0][nt][0], of[0][nt][1], of[0][nt][2], of[0][nt][3],
                         p0[3][0], p0[3][1], p0[3][2], p0[3][3], b2, b3);
                mma_fp16(of[1][nt][0], of[1][nt][1], of[1][nt][2], of[1][nt][3],
                         p1[3][0], p1[3][1], p1[3][2], p1[3][3], b2, b3);
            }
        }
    }

    // lsum: quad-reduce then combine across the jh pair (P region reused)
    __syncthreads();
    float l0s[2], l1s[2];
    #pragma unroll
    for (int qt = 0; qt < 2; ++qt) {
        float a = lsum[qt][0], c = lsum[qt][1];
        a += __shfl_xor_sync(0xFFFFFFFF, a, 1);
        a += __shfl_xor_sync(0xFFFFFFFF, a, 2);
        c += __shfl_xor_sync(0xFFFFFFFF, c, 1);
        c += __shfl_xor_sync(0xFFFFFFFF, c, 2);
        reinterpret_cast<float2*>(dsm + SM_P + (w * 2 + qt) * 256)[lane] = make_float2(a, c);
        l0s[qt] = a; l1s[qt] = c;
    }
    __syncthreads();
    #pragma unroll
    for (int qt = 0; qt < 2; ++qt) {
        float2 o = reinterpret_cast<const float2*>(
            dsm + SM_P + ((w ^ 1) * 2 + qt) * 256)[lane];
        l0s[qt] += o.x;
        l1s[qt] += o.y;
    }

    const float gam = __ldg(gamma);
    const float* xb = x + (size_t)b * Cn * Ln;
    float* ob = out + (size_t)b * Cn * Ln;
    float* Tsm = reinterpret_cast<float*>(dsm + SM_V(0));   // [128 ch][68 q] f32

    #pragma unroll
    for (int qt = 0; qt < 2; ++qt) {
        const float linv0 = 1.f / l0s[qt];
        const float linv1 = 1.f / l1s[qt];
        __syncthreads();
        {
            int q = qg * 16 + (lane >> 2);
            #pragma unroll
            for (int nt = 0; nt < 8; ++nt) {
                int cl = jh * 64 + nt * 8 + (lane & 3) * 2;
                Tsm[cl * 68 + q]           = of[qt][nt][0] * linv0;
                Tsm[(cl + 1) * 68 + q]     = of[qt][nt][1] * linv0;
                Tsm[cl * 68 + q + 8]       = of[qt][nt][2] * linv1;
                Tsm[(cl + 1) * 68 + q + 8] = of[qt][nt][3] * linv1;
            }
        }
        __syncthreads();
        for (int idx = t; idx < 128 * 64; idx += 256) {
            int cl = idx >> 6, qq = idx & 63;
            size_t off = (size_t)(ch_half * 128 + cl) * Ln + i0 + qt * 64 + qq;
            ob[off] = gam * Tsm[cl * 68 + qq] + xb[off];
        }
    }
}

// ===========================================================================
extern "C" void kernel_launch(void* const* d_in, const int* in_sizes, int n_in,
                              void* d_out, int out_size)
{
    const float* x     = (const float*)d_in[0];
    const float* Wq    = (const float*)d_in[1];
    const float* bq    = (const float*)d_in[2];
    const float* Wk    = (const float*)d_in[3];
    const float* bk    = (const float*)d_in[4];
    const float* Wv    = (const float*)d_in[5];
    const float* bv    = (const float*)d_in[6];
    const float* gamma = (const float*)d_in[7];
    float* out = (float*)d_out;

    cudaFuncSetAttribute(qkv_gemm, cudaFuncAttributeMaxDynamicSharedMemorySize, QKV_SMEM);
    cudaFuncSetAttribute(attn_kernel, cudaFuncAttributeMaxDynamicSharedMemorySize, SM_TOTAL);

    qkv_gemm<<<dim3(Ln / 128, Bn), 512, QKV_SMEM>>>(x, Wq, bq, Wk, bk, Wv, bv);
    attn_kernel<<<dim3(Ln / 128, 2, Bn), 256, SM_TOTAL>>>(x, gamma, out);
}